// round 11
// baseline (speedup 1.0000x reference)
#include <cuda_runtime.h>
#include <cuda_fp16.h>
#include <cstdint>

#define BWIN 1024   // windows (batch)
#define LW   64     // window length
#define CH   1024   // channels
#define NH   16     // heads
#define HD   64     // head dim

// Scratch: Q,K as [(b*16+h)][l][d]; V as [(b*16+h)][d][l] (transposed)
__device__ __half g_qkv[3ULL * BWIN * NH * LW * HD];     // 384 MiB
__device__ __half g_xh [(size_t)BWIN * LW * CH];         // 128 MiB
__device__ __half g_wh [3ULL * CH * CH];                 // 6 MiB: W^T [mat][n][k]

__device__ __forceinline__ void mma_f16(float c[4],
                                        uint32_t a0, uint32_t a1, uint32_t a2, uint32_t a3,
                                        uint32_t b0, uint32_t b1) {
    asm volatile(
        "mma.sync.aligned.m16n8k16.row.col.f32.f16.f16.f32 "
        "{%0,%1,%2,%3}, {%4,%5,%6,%7}, {%8,%9}, {%0,%1,%2,%3};\n"
        : "+f"(c[0]), "+f"(c[1]), "+f"(c[2]), "+f"(c[3])
        : "r"(a0), "r"(a1), "r"(a2), "r"(a3), "r"(b0), "r"(b1));
}

#define LDSM_X4(r0, r1, r2, r3, addr) \
    asm volatile("ldmatrix.sync.aligned.m8n8.x4.shared.b16 {%0,%1,%2,%3}, [%4];" \
                 : "=r"(r0), "=r"(r1), "=r"(r2), "=r"(r3) : "r"(addr))

__device__ __forceinline__ uint32_t smem_u32(const void* p) {
    uint32_t a;
    asm("{ .reg .u64 t; cvta.to.shared.u64 t, %1; cvt.u32.u64 %0, t; }" : "=r"(a) : "l"(p));
    return a;
}

__device__ __forceinline__ void cp16(uint32_t dst, const void* src) {
    asm volatile("cp.async.cg.shared.global [%0], [%1], 16;" :: "r"(dst), "l"(src) : "memory");
}
#define CP_COMMIT() asm volatile("cp.async.commit_group;" ::: "memory")
#define CP_WAIT(n)  asm volatile("cp.async.wait_group %0;" :: "n"(n) : "memory")

// ============================================================================
// Prologue: X -> half; W -> half transposed [mat][n][k]
// ============================================================================
__global__ __launch_bounds__(256)
void conv_x_kernel(const float* __restrict__ X)
{
    const size_t i = ((size_t)blockIdx.x * 256 + threadIdx.x) * 8;
    float4 v0 = *reinterpret_cast<const float4*>(X + i);
    float4 v1 = *reinterpret_cast<const float4*>(X + i + 4);
    __half2 h[4];
    h[0] = __floats2half2_rn(v0.x, v0.y);
    h[1] = __floats2half2_rn(v0.z, v0.w);
    h[2] = __floats2half2_rn(v1.x, v1.y);
    h[3] = __floats2half2_rn(v1.z, v1.w);
    *reinterpret_cast<uint4*>(&g_xh[i]) = *reinterpret_cast<uint4*>(h);
}

__global__ __launch_bounds__(256)
void prep_w_kernel(const float* __restrict__ Wq, const float* __restrict__ Wk,
                   const float* __restrict__ Wv)
{
    __shared__ float t[32][33];
    const int mat = blockIdx.z;
    const float* W = (mat == 0) ? Wq : (mat == 1 ? Wk : Wv);
    const int k0 = blockIdx.x * 32, n0 = blockIdx.y * 32;
    const int tx = threadIdx.x & 31, ty = threadIdx.x >> 5;
    #pragma unroll
    for (int i = 0; i < 4; i++) {
        const int r = ty + i * 8;
        t[r][tx] = W[(size_t)(k0 + r) * CH + n0 + tx];
    }
    __syncthreads();
    __half* dst = g_wh + (size_t)mat * CH * CH;
    #pragma unroll
    for (int i = 0; i < 4; i++) {
        const int r = ty + i * 8;
        dst[(size_t)(n0 + r) * CH + k0 + tx] = __float2half_rn(t[tx][r]);
    }
}

// ============================================================================
// Kernel 1: QKV GEMM (r10 config), with m-slice offset for pipelined launch.
//   CTA tile 128x128, 128 thr (4 warps 2x2, warp tile 64x64), k-chunk 64,
//   3-stage cp.async pipeline, frag double-buffer, 2 CTAs/SM.
// ============================================================================

#define ROWB 144              // bytes per smem row (64 halfs + 8 pad)
#define A_ST (128 * ROWB)     // 18432
#define STG  (2 * A_ST)       // 36864
#define NST  3
#define KCH  16               // chunks of k=64
#define GEMM_SMEM (1024 + NST * STG)   // 111616 B

__global__ __launch_bounds__(128, 2)
void qkv_gemm(const float* __restrict__ bq, const float* __restrict__ bk,
              const float* __restrict__ bv, int yoff)
{
    extern __shared__ char smem[];
    float* sBias = reinterpret_cast<float*>(smem);
    const uint32_t sbase = smem_u32(smem);

    const int tid = threadIdx.x;
    const int lane = tid & 31;
    const int warp = tid >> 5;
    const int wm = warp & 1, wn = warp >> 1;

    const int mat = blockIdx.x >> 3;
    const int nb  = (blockIdx.x & 7) * 128;
    const int m0  = (blockIdx.y + yoff) * 128;
    const float* bias = (mat == 0) ? bq : (mat == 1 ? bk : bv);
    sBias[tid] = bias[nb + tid];

    const __half* gA = g_xh + (size_t)m0 * CH;
    const __half* gB = g_wh + (size_t)mat * CH * CH + (size_t)nb * CH;

    const int rw = tid >> 3, cw = tid & 7;   // copies: rows rw + i*16, 16B-col cw

    auto load_chunk = [&](int kc, int s) {
        const uint32_t stA = sbase + 1024 + s * STG;
        const uint32_t stB = stA + A_ST;
        #pragma unroll
        for (int i = 0; i < 8; i++) {
            const int row = rw + i * 16;
            cp16(stA + row * ROWB + cw * 16, gA + (size_t)row * CH + kc * 64 + cw * 8);
            cp16(stB + row * ROWB + cw * 16, gB + (size_t)row * CH + kc * 64 + cw * 8);
        }
        CP_COMMIT();
    };

    load_chunk(0, 0);
    load_chunk(1, 1);
    load_chunk(2, 2);

    float acc[4][8][4];
    #pragma unroll
    for (int mt = 0; mt < 4; mt++)
        #pragma unroll
        for (int nt = 0; nt < 8; nt++)
            #pragma unroll
            for (int j = 0; j < 4; j++) acc[mt][nt][j] = 0.f;

    const uint32_t aoff = (wm * 64 + (lane & 15)) * ROWB + ((lane >> 4) << 4);
    const uint32_t boff = (wn * 64 + (lane & 7) + ((lane >> 4) << 3)) * ROWB
                        + (((lane >> 3) & 1) << 4);

    uint32_t af[2][4][4], bf[2][4][4];

    auto ldsm_frags = [&](uint32_t stA, int ks, int fb) {
        const uint32_t stB = stA + A_ST;
        const uint32_t kbb = ks * 32;
        #pragma unroll
        for (int mt = 0; mt < 4; mt++)
            LDSM_X4(af[fb][mt][0], af[fb][mt][1], af[fb][mt][2], af[fb][mt][3],
                    stA + aoff + mt * (16 * ROWB) + kbb);
        #pragma unroll
        for (int ntp = 0; ntp < 4; ntp++)
            LDSM_X4(bf[fb][ntp][0], bf[fb][ntp][1], bf[fb][ntp][2], bf[fb][ntp][3],
                    stB + boff + ntp * (16 * ROWB) + kbb);
    };

    auto hmma_all = [&](int fb) {
        #pragma unroll
        for (int mt = 0; mt < 4; mt++)
            #pragma unroll
            for (int ntp = 0; ntp < 4; ntp++) {
                mma_f16(acc[mt][2 * ntp],     af[fb][mt][0], af[fb][mt][1], af[fb][mt][2],
                        af[fb][mt][3], bf[fb][ntp][0], bf[fb][ntp][1]);
                mma_f16(acc[mt][2 * ntp + 1], af[fb][mt][0], af[fb][mt][1], af[fb][mt][2],
                        af[fb][mt][3], bf[fb][ntp][2], bf[fb][ntp][3]);
            }
    };

    CP_WAIT(2);
    __syncthreads();
    ldsm_frags(sbase + 1024, 0, 0);

    #pragma unroll 1
    for (int c = 0; c < KCH; ++c) {
        const uint32_t stA = sbase + 1024 + (c % NST) * STG;

        #pragma unroll
        for (int ks = 0; ks < 3; ks++) {
            ldsm_frags(stA, ks + 1, (ks + 1) & 1);
            hmma_all(ks & 1);
        }

        if (c < KCH - 1) {
            if (c < KCH - 2) { CP_WAIT(1); } else { CP_WAIT(0); }
            __syncthreads();
            if (c + 3 < KCH) load_chunk(c + 3, (c + 3) % NST);
            ldsm_frags(sbase + 1024 + ((c + 1) % NST) * STG, 0, 0);
        }

        hmma_all(1);
    }

    // Epilogue: +bias, fp16, scatter. Q,K -> [l][d]; V -> [d][l].
    const size_t matsz = (size_t)BWIN * NH * LW * HD;
    __half* base = g_qkv + (size_t)mat * matsz;
    #pragma unroll
    for (int mt = 0; mt < 4; mt++) {
        const int r0 = m0 + wm * 64 + mt * 16 + (lane >> 2);
        #pragma unroll
        for (int nt = 0; nt < 8; nt++) {
            const int nloc = wn * 64 + nt * 8 + 2 * (lane & 3);
            const int nim = nb + nloc;
            const int h = nim >> 6, d = nim & 63;
            const float bb0 = sBias[nloc], bb1 = sBias[nloc + 1];
            #pragma unroll
            for (int hf = 0; hf < 2; hf++) {
                const int rr = r0 + hf * 8;
                const int bw = rr >> 6, l = rr & 63;
                const float v0 = acc[mt][nt][hf * 2 + 0] + bb0;
                const float v1 = acc[mt][nt][hf * 2 + 1] + bb1;
                if (mat < 2) {
                    const size_t o = (((size_t)bw * NH + h) * LW + l) * HD + d;
                    *reinterpret_cast<__half2*>(&base[o]) = __floats2half2_rn(v0, v1);
                } else {
                    const size_t o = (((size_t)bw * NH + h) * HD + d) * LW + l;
                    base[o]      = __float2half_rn(v0);
                    base[o + LW] = __float2half_rn(v1);
                }
            }
        }
    }
}

// ============================================================================
// Kernel 2: windowed attention (r10), with window-slice offset.
// ============================================================================

__global__ __launch_bounds__(128, 4)
void attn_kernel(const float* __restrict__ bias_table, float* __restrict__ out, int woff)
{
    __shared__ __half qs [64 * 72];
    __shared__ __half ksm[64 * 72];
    __shared__ __half vts[64 * 72];   // V^T: [d][j]
    __shared__ float sBias[128];

    const int h = blockIdx.x, b = blockIdx.y + woff;
    const int tid = threadIdx.x, lane = tid & 31, warp = tid >> 5;

    const size_t tile = (size_t)(b * NH + h) * (LW * HD);
    const size_t matsz = (size_t)BWIN * NH * LW * HD;
    const __half* gq = g_qkv + tile;
    const __half* gk = g_qkv + matsz + tile;
    const __half* gv = g_qkv + 2 * matsz + tile;

    #pragma unroll
    for (int i = 0; i < 4; i++) {
        const int f = i * 128 + tid;
        const int row = f >> 3, c16 = f & 7;
        uint4 q4 = *reinterpret_cast<const uint4*>(gq + row * 64 + c16 * 8);
        uint4 k4 = *reinterpret_cast<const uint4*>(gk + row * 64 + c16 * 8);
        uint4 v4 = *reinterpret_cast<const uint4*>(gv + row * 64 + c16 * 8);
        *reinterpret_cast<uint4*>(reinterpret_cast<char*>(qs)  + row * 144 + c16 * 16) = q4;
        *reinterpret_cast<uint4*>(reinterpret_cast<char*>(ksm) + row * 144 + c16 * 16) = k4;
        *reinterpret_cast<uint4*>(reinterpret_cast<char*>(vts) + row * 144 + c16 * 16) = v4;
    }
    if (tid < 127) sBias[tid] = bias_table[tid * NH + h];
    __syncthreads();

    const int i0 = warp * 16 + (lane >> 2);
    const uint32_t* wQ = reinterpret_cast<const uint32_t*>(qs);
    const uint32_t* wK = reinterpret_cast<const uint32_t*>(ksm);
    const uint32_t* wV = reinterpret_cast<const uint32_t*>(vts);

    float s[8][4];
    #pragma unroll
    for (int nt = 0; nt < 8; nt++)
        #pragma unroll
        for (int j = 0; j < 4; j++) s[nt][j] = 0.f;

    #pragma unroll
    for (int ks = 0; ks < 4; ks++) {
        const int kw = ks * 8 + (lane & 3);
        const uint32_t a0 = wQ[i0 * 36 + kw];
        const uint32_t a1 = wQ[(i0 + 8) * 36 + kw];
        const uint32_t a2 = wQ[i0 * 36 + kw + 4];
        const uint32_t a3 = wQ[(i0 + 8) * 36 + kw + 4];
        #pragma unroll
        for (int nt = 0; nt < 8; nt++) {
            const int col = nt * 8 + (lane >> 2);
            mma_f16(s[nt], a0, a1, a2, a3, wK[col * 36 + kw], wK[col * 36 + kw + 4]);
        }
    }

    float mx0 = -1e30f, mx1 = -1e30f;
    #pragma unroll
    for (int nt = 0; nt < 8; nt++) {
        const int j0 = nt * 8 + 2 * (lane & 3);
        float v00 = s[nt][0] * 0.125f + sBias[i0 - j0 + 63];
        float v01 = s[nt][1] * 0.125f + sBias[i0 - j0 + 62];
        float v10 = s[nt][2] * 0.125f + sBias[i0 + 8 - j0 + 63];
        float v11 = s[nt][3] * 0.125f + sBias[i0 + 8 - j0 + 62];
        s[nt][0] = v00; s[nt][1] = v01; s[nt][2] = v10; s[nt][3] = v11;
        mx0 = fmaxf(mx0, fmaxf(v00, v01));
        mx1 = fmaxf(mx1, fmaxf(v10, v11));
    }
    mx0 = fmaxf(mx0, __shfl_xor_sync(0xffffffffu, mx0, 1));
    mx0 = fmaxf(mx0, __shfl_xor_sync(0xffffffffu, mx0, 2));
    mx1 = fmaxf(mx1, __shfl_xor_sync(0xffffffffu, mx1, 1));
    mx1 = fmaxf(mx1, __shfl_xor_sync(0xffffffffu, mx1, 2));

    float sum0 = 0.f, sum1 = 0.f;
    #pragma unroll
    for (int nt = 0; nt < 8; nt++) {
        s[nt][0] = __expf(s[nt][0] - mx0);
        s[nt][1] = __expf(s[nt][1] - mx0);
        s[nt][2] = __expf(s[nt][2] - mx1);
        s[nt][3] = __expf(s[nt][3] - mx1);
        sum0 += s[nt][0] + s[nt][1];
        sum1 += s[nt][2] + s[nt][3];
    }
    sum0 += __shfl_xor_sync(0xffffffffu, sum0, 1);
    sum0 += __shfl_xor_sync(0xffffffffu, sum0, 2);
    sum1 += __shfl_xor_sync(0xffffffffu, sum1, 1);
    sum1 += __shfl_xor_sync(0xffffffffu, sum1, 2);

    float o[8][4];
    #pragma unroll
    for (int nt = 0; nt < 8; nt++)
        #pragma unroll
        for (int j = 0; j < 4; j++) o[nt][j] = 0.f;

    #pragma unroll
    for (int ks = 0; ks < 4; ks++) {
        __half2 ah[4];
        ah[0] = __floats2half2_rn(s[2 * ks][0],     s[2 * ks][1]);
        ah[1] = __floats2half2_rn(s[2 * ks][2],     s[2 * ks][3]);
        ah[2] = __floats2half2_rn(s[2 * ks + 1][0], s[2 * ks + 1][1]);
        ah[3] = __floats2half2_rn(s[2 * ks + 1][2], s[2 * ks + 1][3]);
        const uint32_t a0 = *reinterpret_cast<uint32_t*>(&ah[0]);
        const uint32_t a1 = *reinterpret_cast<uint32_t*>(&ah[1]);
        const uint32_t a2 = *reinterpret_cast<uint32_t*>(&ah[2]);
        const uint32_t a3 = *reinterpret_cast<uint32_t*>(&ah[3]);
        const int kw = ks * 8 + (lane & 3);
        #pragma unroll
        for (int nt = 0; nt < 8; nt++) {
            const int d = nt * 8 + (lane >> 2);
            mma_f16(o[nt], a0, a1, a2, a3, wV[d * 36 + kw], wV[d * 36 + kw + 4]);
        }
    }

    const float inv0 = 1.0f / sum0;
    const float inv1 = 1.0f / sum1;

    #pragma unroll
    for (int nt = 0; nt < 8; nt++) {
        const int d = nt * 8 + 2 * (lane & 3);
        const size_t o0 = ((size_t)(b * LW + i0)) * CH + h * HD + d;
        const size_t o1 = ((size_t)(b * LW + i0 + 8)) * CH + h * HD + d;
        *reinterpret_cast<float2*>(&out[o0]) = make_float2(o[nt][0] * inv0, o[nt][1] * inv0);
        *reinterpret_cast<float2*>(&out[o1]) = make_float2(o[nt][2] * inv1, o[nt][3] * inv1);
    }
}

// ============================================================================
// Launch: fork-join pipelined slices — attn slice i (stream s2) overlaps
// GEMM slice i+1 (stream 0). Cross-stream events become graph edges.
// ============================================================================

#define NSLICE 4

extern "C" void kernel_launch(void* const* d_in, const int* in_sizes, int n_in,
                              void* d_out, int out_size)
{
    const float* X   = (const float*)d_in[0];
    const float* Wq  = (const float*)d_in[1];
    const float* bq  = (const float*)d_in[2];
    const float* Wk  = (const float*)d_in[3];
    const float* bk  = (const float*)d_in[4];
    const float* Wv  = (const float*)d_in[5];
    const float* bv  = (const float*)d_in[6];
    const float* bt  = (const float*)d_in[7];
    float* out = (float*)d_out;

    static cudaStream_t s2 = nullptr;
    static cudaEvent_t evG[NSLICE], evA[NSLICE];
    if (s2 == nullptr) {
        cudaStreamCreateWithFlags(&s2, cudaStreamNonBlocking);
        for (int i = 0; i < NSLICE; i++) {
            cudaEventCreateWithFlags(&evG[i], cudaEventDisableTiming);
            cudaEventCreateWithFlags(&evA[i], cudaEventDisableTiming);
        }
        cudaFuncSetAttribute(qkv_gemm, cudaFuncAttributeMaxDynamicSharedMemorySize,
                             GEMM_SMEM);
    }

    conv_x_kernel<<<(BWIN * LW * CH) / (256 * 8), 256>>>(X);
    prep_w_kernel<<<dim3(32, 32, 3), 256>>>(Wq, Wk, Wv);

    const int ySlice = 512 / NSLICE;     // m-tiles per slice
    const int wSlice = BWIN / NSLICE;    // windows per slice

    for (int i = 0; i < NSLICE; i++) {
        qkv_gemm<<<dim3(24, ySlice), 128, GEMM_SMEM>>>(bq, bk, bv, i * ySlice);
        cudaEventRecord(evG[i], 0);
    }
    for (int i = 0; i < NSLICE; i++) {
        cudaStreamWaitEvent(s2, evG[i], 0);
        attn_kernel<<<dim3(NH, wSlice), 128, 0, s2>>>(bt, out, i * wSlice);
        cudaEventRecord(evA[i], s2);
    }
    for (int i = 0; i < NSLICE; i++)
        cudaStreamWaitEvent(0, evA[i], 0);
}

// round 13
// speedup vs baseline: 1.5517x; 1.5517x over previous
#include <cuda_runtime.h>
#include <cuda_fp16.h>
#include <cstdint>

#define BWIN 1024   // windows (batch)
#define LW   64     // window length
#define CH   1024   // channels
#define NH   16     // heads
#define HD   64     // head dim

// Scratch: Q,K as [(b*16+h)][l][d]; V as [(b*16+h)][d][l] (transposed)
__device__ __half g_qkv[3ULL * BWIN * NH * LW * HD];     // 384 MiB
__device__ __half g_xh [(size_t)BWIN * LW * CH];         // 128 MiB
__device__ __half g_wh [3ULL * CH * CH];                 // 6 MiB: W^T [mat][n][k]

__device__ __forceinline__ void mma_f16(float c[4],
                                        uint32_t a0, uint32_t a1, uint32_t a2, uint32_t a3,
                                        uint32_t b0, uint32_t b1) {
    asm volatile(
        "mma.sync.aligned.m16n8k16.row.col.f32.f16.f16.f32 "
        "{%0,%1,%2,%3}, {%4,%5,%6,%7}, {%8,%9}, {%0,%1,%2,%3};\n"
        : "+f"(c[0]), "+f"(c[1]), "+f"(c[2]), "+f"(c[3])
        : "r"(a0), "r"(a1), "r"(a2), "r"(a3), "r"(b0), "r"(b1));
}

#define LDSM_X4(r0, r1, r2, r3, addr) \
    asm volatile("ldmatrix.sync.aligned.m8n8.x4.shared.b16 {%0,%1,%2,%3}, [%4];" \
                 : "=r"(r0), "=r"(r1), "=r"(r2), "=r"(r3) : "r"(addr))

__device__ __forceinline__ uint32_t smem_u32(const void* p) {
    uint32_t a;
    asm("{ .reg .u64 t; cvta.to.shared.u64 t, %1; cvt.u32.u64 %0, t; }" : "=r"(a) : "l"(p));
    return a;
}

__device__ __forceinline__ void cp16(uint32_t dst, const void* src) {
    asm volatile("cp.async.cg.shared.global [%0], [%1], 16;" :: "r"(dst), "l"(src) : "memory");
}
#define CP_COMMIT() asm volatile("cp.async.commit_group;" ::: "memory")
#define CP_WAIT(n)  asm volatile("cp.async.wait_group %0;" :: "n"(n) : "memory")

// ============================================================================
// Prologue: X -> half; W -> half transposed [mat][n][k]
// ============================================================================
__global__ __launch_bounds__(256)
void conv_x_kernel(const float* __restrict__ X)
{
    const size_t i = ((size_t)blockIdx.x * 256 + threadIdx.x) * 8;
    float4 v0 = *reinterpret_cast<const float4*>(X + i);
    float4 v1 = *reinterpret_cast<const float4*>(X + i + 4);
    __half2 h[4];
    h[0] = __floats2half2_rn(v0.x, v0.y);
    h[1] = __floats2half2_rn(v0.z, v0.w);
    h[2] = __floats2half2_rn(v1.x, v1.y);
    h[3] = __floats2half2_rn(v1.z, v1.w);
    *reinterpret_cast<uint4*>(&g_xh[i]) = *reinterpret_cast<uint4*>(h);
}

__global__ __launch_bounds__(256)
void prep_w_kernel(const float* __restrict__ Wq, const float* __restrict__ Wk,
                   const float* __restrict__ Wv)
{
    __shared__ float t[32][33];
    const int mat = blockIdx.z;
    const float* W = (mat == 0) ? Wq : (mat == 1 ? Wk : Wv);
    const int k0 = blockIdx.x * 32, n0 = blockIdx.y * 32;
    const int tx = threadIdx.x & 31, ty = threadIdx.x >> 5;
    #pragma unroll
    for (int i = 0; i < 4; i++) {
        const int r = ty + i * 8;
        t[r][tx] = W[(size_t)(k0 + r) * CH + n0 + tx];
    }
    __syncthreads();
    __half* dst = g_wh + (size_t)mat * CH * CH;
    #pragma unroll
    for (int i = 0; i < 4; i++) {
        const int r = ty + i * 8;
        dst[(size_t)(n0 + r) * CH + k0 + tx] = __float2half_rn(t[tx][r]);
    }
}

// ============================================================================
// Kernel 1: QKV GEMM (r10 config — best known).
//   CTA tile 128x128, 128 thr (4 warps 2x2, warp tile 64x64), k-chunk 64,
//   3-stage cp.async pipeline, frag double-buffer, 2 CTAs/SM, 16 barriers.
//   Grid (24, 512), x = {mat x n-tile} fastest for L2 A-reuse.
// ============================================================================

#define ROWB 144              // bytes per smem row (64 halfs + 8 pad)
#define A_ST (128 * ROWB)     // 18432
#define STG  (2 * A_ST)       // 36864
#define NST  3
#define KCH  16               // chunks of k=64
#define GEMM_SMEM (1024 + NST * STG)   // 111616 B

__global__ __launch_bounds__(128, 2)
void qkv_gemm(const float* __restrict__ bq, const float* __restrict__ bk,
              const float* __restrict__ bv)
{
    extern __shared__ char smem[];
    float* sBias = reinterpret_cast<float*>(smem);
    const uint32_t sbase = smem_u32(smem);

    const int tid = threadIdx.x;
    const int lane = tid & 31;
    const int warp = tid >> 5;
    const int wm = warp & 1, wn = warp >> 1;

    const int mat = blockIdx.x >> 3;
    const int nb  = (blockIdx.x & 7) * 128;
    const int m0  = blockIdx.y * 128;
    const float* bias = (mat == 0) ? bq : (mat == 1 ? bk : bv);
    sBias[tid] = bias[nb + tid];

    const __half* gA = g_xh + (size_t)m0 * CH;
    const __half* gB = g_wh + (size_t)mat * CH * CH + (size_t)nb * CH;

    const int rw = tid >> 3, cw = tid & 7;   // copies: rows rw + i*16, 16B-col cw

    auto load_chunk = [&](int kc, int s) {
        const uint32_t stA = sbase + 1024 + s * STG;
        const uint32_t stB = stA + A_ST;
        #pragma unroll
        for (int i = 0; i < 8; i++) {
            const int row = rw + i * 16;
            cp16(stA + row * ROWB + cw * 16, gA + (size_t)row * CH + kc * 64 + cw * 8);
            cp16(stB + row * ROWB + cw * 16, gB + (size_t)row * CH + kc * 64 + cw * 8);
        }
        CP_COMMIT();
    };

    load_chunk(0, 0);
    load_chunk(1, 1);
    load_chunk(2, 2);

    float acc[4][8][4];
    #pragma unroll
    for (int mt = 0; mt < 4; mt++)
        #pragma unroll
        for (int nt = 0; nt < 8; nt++)
            #pragma unroll
            for (int j = 0; j < 4; j++) acc[mt][nt][j] = 0.f;

    const uint32_t aoff = (wm * 64 + (lane & 15)) * ROWB + ((lane >> 4) << 4);
    const uint32_t boff = (wn * 64 + (lane & 7) + ((lane >> 4) << 3)) * ROWB
                        + (((lane >> 3) & 1) << 4);

    uint32_t af[2][4][4], bf[2][4][4];

    auto ldsm_frags = [&](uint32_t stA, int ks, int fb) {
        const uint32_t stB = stA + A_ST;
        const uint32_t kbb = ks * 32;
        #pragma unroll
        for (int mt = 0; mt < 4; mt++)
            LDSM_X4(af[fb][mt][0], af[fb][mt][1], af[fb][mt][2], af[fb][mt][3],
                    stA + aoff + mt * (16 * ROWB) + kbb);
        #pragma unroll
        for (int ntp = 0; ntp < 4; ntp++)
            LDSM_X4(bf[fb][ntp][0], bf[fb][ntp][1], bf[fb][ntp][2], bf[fb][ntp][3],
                    stB + boff + ntp * (16 * ROWB) + kbb);
    };

    auto hmma_all = [&](int fb) {
        #pragma unroll
        for (int mt = 0; mt < 4; mt++)
            #pragma unroll
            for (int ntp = 0; ntp < 4; ntp++) {
                mma_f16(acc[mt][2 * ntp],     af[fb][mt][0], af[fb][mt][1], af[fb][mt][2],
                        af[fb][mt][3], bf[fb][ntp][0], bf[fb][ntp][1]);
                mma_f16(acc[mt][2 * ntp + 1], af[fb][mt][0], af[fb][mt][1], af[fb][mt][2],
                        af[fb][mt][3], bf[fb][ntp][2], bf[fb][ntp][3]);
            }
    };

    CP_WAIT(2);
    __syncthreads();
    ldsm_frags(sbase + 1024, 0, 0);

    #pragma unroll 1
    for (int c = 0; c < KCH; ++c) {
        const uint32_t stA = sbase + 1024 + (c % NST) * STG;

        #pragma unroll
        for (int ks = 0; ks < 3; ks++) {
            ldsm_frags(stA, ks + 1, (ks + 1) & 1);
            hmma_all(ks & 1);
        }

        if (c < KCH - 1) {
            if (c < KCH - 2) { CP_WAIT(1); } else { CP_WAIT(0); }
            __syncthreads();
            if (c + 3 < KCH) load_chunk(c + 3, (c + 3) % NST);
            ldsm_frags(sbase + 1024 + ((c + 1) % NST) * STG, 0, 0);
        }

        hmma_all(1);
    }

    // Epilogue: +bias, fp16, scatter with streaming (evict-first) stores.
    const size_t matsz = (size_t)BWIN * NH * LW * HD;
    __half* base = g_qkv + (size_t)mat * matsz;
    #pragma unroll
    for (int mt = 0; mt < 4; mt++) {
        const int r0 = m0 + wm * 64 + mt * 16 + (lane >> 2);
        #pragma unroll
        for (int nt = 0; nt < 8; nt++) {
            const int nloc = wn * 64 + nt * 8 + 2 * (lane & 3);
            const int nim = nb + nloc;
            const int h = nim >> 6, d = nim & 63;
            const float bb0 = sBias[nloc], bb1 = sBias[nloc + 1];
            #pragma unroll
            for (int hf = 0; hf < 2; hf++) {
                const int rr = r0 + hf * 8;
                const int bw = rr >> 6, l = rr & 63;
                const float v0 = acc[mt][nt][hf * 2 + 0] + bb0;
                const float v1 = acc[mt][nt][hf * 2 + 1] + bb1;
                if (mat < 2) {
                    const size_t o = (((size_t)bw * NH + h) * LW + l) * HD + d;
                    __half2 hv = __floats2half2_rn(v0, v1);
                    __stcs(reinterpret_cast<unsigned int*>(&base[o]),
                           *reinterpret_cast<unsigned int*>(&hv));
                } else {
                    const size_t o = (((size_t)bw * NH + h) * HD + d) * LW + l;
                    base[o]      = __float2half_rn(v0);
                    base[o + LW] = __float2half_rn(v1);
                }
            }
        }
    }
}

// ============================================================================
// Kernel 2: windowed attention, fp16 mma, P in registers. 6 CTAs/SM.
// ============================================================================

__global__ __launch_bounds__(128, 6)
void attn_kernel(const float* __restrict__ bias_table, float* __restrict__ out)
{
    __shared__ __half qs [64 * 72];
    __shared__ __half ksm[64 * 72];
    __shared__ __half vts[64 * 72];   // V^T: [d][j]
    __shared__ float sBias[128];

    const int h = blockIdx.x, b = blockIdx.y;
    const int tid = threadIdx.x, lane = tid & 31, warp = tid >> 5;

    const size_t tile = (size_t)(b * NH + h) * (LW * HD);
    const size_t matsz = (size_t)BWIN * NH * LW * HD;
    const __half* gq = g_qkv + tile;
    const __half* gk = g_qkv + matsz + tile;
    const __half* gv = g_qkv + 2 * matsz + tile;

    #pragma unroll
    for (int i = 0; i < 4; i++) {
        const int f = i * 128 + tid;
        const int row = f >> 3, c16 = f & 7;
        uint4 q4 = __ldcs(reinterpret_cast<const uint4*>(gq + row * 64 + c16 * 8));
        uint4 k4 = __ldcs(reinterpret_cast<const uint4*>(gk + row * 64 + c16 * 8));
        uint4 v4 = __ldcs(reinterpret_cast<const uint4*>(gv + row * 64 + c16 * 8));
        *reinterpret_cast<uint4*>(reinterpret_cast<char*>(qs)  + row * 144 + c16 * 16) = q4;
        *reinterpret_cast<uint4*>(reinterpret_cast<char*>(ksm) + row * 144 + c16 * 16) = k4;
        *reinterpret_cast<uint4*>(reinterpret_cast<char*>(vts) + row * 144 + c16 * 16) = v4;
    }
    if (tid < 127) sBias[tid] = bias_table[tid * NH + h];
    __syncthreads();

    const int i0 = warp * 16 + (lane >> 2);
    const uint32_t* wQ = reinterpret_cast<const uint32_t*>(qs);
    const uint32_t* wK = reinterpret_cast<const uint32_t*>(ksm);
    const uint32_t* wV = reinterpret_cast<const uint32_t*>(vts);

    float s[8][4];
    #pragma unroll
    for (int nt = 0; nt < 8; nt++)
        #pragma unroll
        for (int j = 0; j < 4; j++) s[nt][j] = 0.f;

    #pragma unroll
    for (int ks = 0; ks < 4; ks++) {
        const int kw = ks * 8 + (lane & 3);
        const uint32_t a0 = wQ[i0 * 36 + kw];
        const uint32_t a1 = wQ[(i0 + 8) * 36 + kw];
        const uint32_t a2 = wQ[i0 * 36 + kw + 4];
        const uint32_t a3 = wQ[(i0 + 8) * 36 + kw + 4];
        #pragma unroll
        for (int nt = 0; nt < 8; nt++) {
            const int col = nt * 8 + (lane >> 2);
            mma_f16(s[nt], a0, a1, a2, a3, wK[col * 36 + kw], wK[col * 36 + kw + 4]);
        }
    }

    float mx0 = -1e30f, mx1 = -1e30f;
    #pragma unroll
    for (int nt = 0; nt < 8; nt++) {
        const int j0 = nt * 8 + 2 * (lane & 3);
        float v00 = s[nt][0] * 0.125f + sBias[i0 - j0 + 63];
        float v01 = s[nt][1] * 0.125f + sBias[i0 - j0 + 62];
        float v10 = s[nt][2] * 0.125f + sBias[i0 + 8 - j0 + 63];
        float v11 = s[nt][3] * 0.125f + sBias[i0 + 8 - j0 + 62];
        s[nt][0] = v00; s[nt][1] = v01; s[nt][2] = v10; s[nt][3] = v11;
        mx0 = fmaxf(mx0, fmaxf(v00, v01));
        mx1 = fmaxf(mx1, fmaxf(v10, v11));
    }
    mx0 = fmaxf(mx0, __shfl_xor_sync(0xffffffffu, mx0, 1));
    mx0 = fmaxf(mx0, __shfl_xor_sync(0xffffffffu, mx0, 2));
    mx1 = fmaxf(mx1, __shfl_xor_sync(0xffffffffu, mx1, 1));
    mx1 = fmaxf(mx1, __shfl_xor_sync(0xffffffffu, mx1, 2));

    float sum0 = 0.f, sum1 = 0.f;
    #pragma unroll
    for (int nt = 0; nt < 8; nt++) {
        s[nt][0] = __expf(s[nt][0] - mx0);
        s[nt][1] = __expf(s[nt][1] - mx0);
        s[nt][2] = __expf(s[nt][2] - mx1);
        s[nt][3] = __expf(s[nt][3] - mx1);
        sum0 += s[nt][0] + s[nt][1];
        sum1 += s[nt][2] + s[nt][3];
    }
    sum0 += __shfl_xor_sync(0xffffffffu, sum0, 1);
    sum0 += __shfl_xor_sync(0xffffffffu, sum0, 2);
    sum1 += __shfl_xor_sync(0xffffffffu, sum1, 1);
    sum1 += __shfl_xor_sync(0xffffffffu, sum1, 2);

    float o[8][4];
    #pragma unroll
    for (int nt = 0; nt < 8; nt++)
        #pragma unroll
        for (int j = 0; j < 4; j++) o[nt][j] = 0.f;

    #pragma unroll
    for (int ks = 0; ks < 4; ks++) {
        __half2 ah[4];
        ah[0] = __floats2half2_rn(s[2 * ks][0],     s[2 * ks][1]);
        ah[1] = __floats2half2_rn(s[2 * ks][2],     s[2 * ks][3]);
        ah[2] = __floats2half2_rn(s[2 * ks + 1][0], s[2 * ks + 1][1]);
        ah[3] = __floats2half2_rn(s[2 * ks + 1][2], s[2 * ks + 1][3]);
        const uint32_t a0 = *reinterpret_cast<uint32_t*>(&ah[0]);
        const uint32_t a1 = *reinterpret_cast<uint32_t*>(&ah[1]);
        const uint32_t a2 = *reinterpret_cast<uint32_t*>(&ah[2]);
        const uint32_t a3 = *reinterpret_cast<uint32_t*>(&ah[3]);
        const int kw = ks * 8 + (lane & 3);
        #pragma unroll
        for (int nt = 0; nt < 8; nt++) {
            const int d = nt * 8 + (lane >> 2);
            mma_f16(o[nt], a0, a1, a2, a3, wV[d * 36 + kw], wV[d * 36 + kw + 4]);
        }
    }

    const float inv0 = 1.0f / sum0;
    const float inv1 = 1.0f / sum1;

    #pragma unroll
    for (int nt = 0; nt < 8; nt++) {
        const int d = nt * 8 + 2 * (lane & 3);
        const size_t o0 = ((size_t)(b * LW + i0)) * CH + h * HD + d;
        const size_t o1 = ((size_t)(b * LW + i0 + 8)) * CH + h * HD + d;
        __stcs(reinterpret_cast<float2*>(&out[o0]),
               make_float2(o[nt][0] * inv0, o[nt][1] * inv0));
        __stcs(reinterpret_cast<float2*>(&out[o1]),
               make_float2(o[nt][2] * inv1, o[nt][3] * inv1));
    }
}

// ============================================================================

extern "C" void kernel_launch(void* const* d_in, const int* in_sizes, int n_in,
                              void* d_out, int out_size)
{
    const float* X   = (const float*)d_in[0];
    const float* Wq  = (const float*)d_in[1];
    const float* bq  = (const float*)d_in[2];
    const float* Wk  = (const float*)d_in[3];
    const float* bk  = (const float*)d_in[4];
    const float* Wv  = (const float*)d_in[5];
    const float* bv  = (const float*)d_in[6];
    const float* bt  = (const float*)d_in[7];
    float* out = (float*)d_out;

    static cudaStream_t s2 = nullptr;
    static cudaEvent_t e0 = nullptr, e1 = nullptr;
    if (s2 == nullptr) {
        cudaStreamCreateWithFlags(&s2, cudaStreamNonBlocking);
        cudaEventCreateWithFlags(&e0, cudaEventDisableTiming);
        cudaEventCreateWithFlags(&e1, cudaEventDisableTiming);
        cudaFuncSetAttribute(qkv_gemm, cudaFuncAttributeMaxDynamicSharedMemorySize,
                             GEMM_SMEM);
    }

    // prep_w (s2) runs concurrently with conv_x (stream 0); join before GEMM.
    cudaEventRecord(e0, 0);
    cudaStreamWaitEvent(s2, e0, 0);
    prep_w_kernel<<<dim3(32, 32, 3), 256, 0, s2>>>(Wq, Wk, Wv);
    cudaEventRecord(e1, s2);

    conv_x_kernel<<<(BWIN * LW * CH) / (256 * 8), 256>>>(X);
    cudaStreamWaitEvent(0, e1, 0);

    qkv_gemm<<<dim3(24, 512), 128, GEMM_SMEM>>>(bq, bk, bv);
    attn_kernel<<<dim3(NH, BWIN), 128>>>(bt, out);
}

// round 14
// speedup vs baseline: 1.5631x; 1.0073x over previous
#include <cuda_runtime.h>
#include <cuda_fp16.h>
#include <cstdint>

#define BWIN 1024   // windows (batch)
#define LW   64     // window length
#define CH   1024   // channels
#define NH   16     // heads
#define HD   64     // head dim

// Scratch: Q,K as [(b*16+h)][l][d]; V as [(b*16+h)][d][l] (transposed)
__device__ __half g_qkv[3ULL * BWIN * NH * LW * HD];     // 384 MiB
__device__ __half g_xh [(size_t)BWIN * LW * CH];         // 128 MiB
__device__ __half g_wh [3ULL * CH * CH];                 // 6 MiB: W^T [mat][n][k]

__device__ __forceinline__ void mma_f16(float c[4],
                                        uint32_t a0, uint32_t a1, uint32_t a2, uint32_t a3,
                                        uint32_t b0, uint32_t b1) {
    asm volatile(
        "mma.sync.aligned.m16n8k16.row.col.f32.f16.f16.f32 "
        "{%0,%1,%2,%3}, {%4,%5,%6,%7}, {%8,%9}, {%0,%1,%2,%3};\n"
        : "+f"(c[0]), "+f"(c[1]), "+f"(c[2]), "+f"(c[3])
        : "r"(a0), "r"(a1), "r"(a2), "r"(a3), "r"(b0), "r"(b1));
}

#define LDSM_X4(r0, r1, r2, r3, addr) \
    asm volatile("ldmatrix.sync.aligned.m8n8.x4.shared.b16 {%0,%1,%2,%3}, [%4];" \
                 : "=r"(r0), "=r"(r1), "=r"(r2), "=r"(r3) : "r"(addr))

__device__ __forceinline__ uint32_t smem_u32(const void* p) {
    uint32_t a;
    asm("{ .reg .u64 t; cvta.to.shared.u64 t, %1; cvt.u32.u64 %0, t; }" : "=r"(a) : "l"(p));
    return a;
}

__device__ __forceinline__ void cp16(uint32_t dst, const void* src) {
    asm volatile("cp.async.cg.shared.global [%0], [%1], 16;" :: "r"(dst), "l"(src) : "memory");
}
#define CP_COMMIT() asm volatile("cp.async.commit_group;" ::: "memory")
#define CP_WAIT(n)  asm volatile("cp.async.wait_group %0;" :: "n"(n) : "memory")

// ============================================================================
// Prologue: X -> half; W -> half transposed [mat][n][k]
// ============================================================================
__global__ __launch_bounds__(256)
void conv_x_kernel(const float* __restrict__ X)
{
    const size_t i = ((size_t)blockIdx.x * 256 + threadIdx.x) * 8;
    float4 v0 = *reinterpret_cast<const float4*>(X + i);
    float4 v1 = *reinterpret_cast<const float4*>(X + i + 4);
    __half2 h[4];
    h[0] = __floats2half2_rn(v0.x, v0.y);
    h[1] = __floats2half2_rn(v0.z, v0.w);
    h[2] = __floats2half2_rn(v1.x, v1.y);
    h[3] = __floats2half2_rn(v1.z, v1.w);
    *reinterpret_cast<uint4*>(&g_xh[i]) = *reinterpret_cast<uint4*>(h);
}

__global__ __launch_bounds__(256)
void prep_w_kernel(const float* __restrict__ Wq, const float* __restrict__ Wk,
                   const float* __restrict__ Wv)
{
    __shared__ float t[32][33];
    const int mat = blockIdx.z;
    const float* W = (mat == 0) ? Wq : (mat == 1 ? Wk : Wv);
    const int k0 = blockIdx.x * 32, n0 = blockIdx.y * 32;
    const int tx = threadIdx.x & 31, ty = threadIdx.x >> 5;
    #pragma unroll
    for (int i = 0; i < 4; i++) {
        const int r = ty + i * 8;
        t[r][tx] = W[(size_t)(k0 + r) * CH + n0 + tx];
    }
    __syncthreads();
    __half* dst = g_wh + (size_t)mat * CH * CH;
    #pragma unroll
    for (int i = 0; i < 4; i++) {
        const int r = ty + i * 8;
        dst[(size_t)(n0 + r) * CH + k0 + tx] = __float2half_rn(t[tx][r]);
    }
}

// ============================================================================
// Kernel 1: QKV GEMM (r10 mainloop — best known).
//   CTA tile 128x128, 128 thr (4 warps 2x2, warp tile 64x64), k-chunk 64,
//   3-stage cp.async pipeline, frag double-buffer, 2 CTAs/SM, 16 barriers.
//   V epilogue staged through (now-free) pipeline smem for coalesced stores.
// ============================================================================

#define ROWB 144              // bytes per smem row (64 halfs + 8 pad)
#define A_ST (128 * ROWB)     // 18432
#define STG  (2 * A_ST)       // 36864
#define NST  3
#define KCH  16               // chunks of k=64
#define GEMM_SMEM (1024 + NST * STG)   // 111616 B
#define SCW 136               // V staging row stride (halfs)

__global__ __launch_bounds__(128, 2)
void qkv_gemm(const float* __restrict__ bq, const float* __restrict__ bk,
              const float* __restrict__ bv)
{
    extern __shared__ char smem[];
    float* sBias = reinterpret_cast<float*>(smem);
    const uint32_t sbase = smem_u32(smem);

    const int tid = threadIdx.x;
    const int lane = tid & 31;
    const int warp = tid >> 5;
    const int wm = warp & 1, wn = warp >> 1;

    const int mat = blockIdx.x >> 3;
    const int nb  = (blockIdx.x & 7) * 128;
    const int m0  = blockIdx.y * 128;
    const float* bias = (mat == 0) ? bq : (mat == 1 ? bk : bv);
    sBias[tid] = bias[nb + tid];

    const __half* gA = g_xh + (size_t)m0 * CH;
    const __half* gB = g_wh + (size_t)mat * CH * CH + (size_t)nb * CH;

    const int rw = tid >> 3, cw = tid & 7;   // copies: rows rw + i*16, 16B-col cw

    auto load_chunk = [&](int kc, int s) {
        const uint32_t stA = sbase + 1024 + s * STG;
        const uint32_t stB = stA + A_ST;
        #pragma unroll
        for (int i = 0; i < 8; i++) {
            const int row = rw + i * 16;
            cp16(stA + row * ROWB + cw * 16, gA + (size_t)row * CH + kc * 64 + cw * 8);
            cp16(stB + row * ROWB + cw * 16, gB + (size_t)row * CH + kc * 64 + cw * 8);
        }
        CP_COMMIT();
    };

    load_chunk(0, 0);
    load_chunk(1, 1);
    load_chunk(2, 2);

    float acc[4][8][4];
    #pragma unroll
    for (int mt = 0; mt < 4; mt++)
        #pragma unroll
        for (int nt = 0; nt < 8; nt++)
            #pragma unroll
            for (int j = 0; j < 4; j++) acc[mt][nt][j] = 0.f;

    const uint32_t aoff = (wm * 64 + (lane & 15)) * ROWB + ((lane >> 4) << 4);
    const uint32_t boff = (wn * 64 + (lane & 7) + ((lane >> 4) << 3)) * ROWB
                        + (((lane >> 3) & 1) << 4);

    uint32_t af[2][4][4], bf[2][4][4];

    auto ldsm_frags = [&](uint32_t stA, int ks, int fb) {
        const uint32_t stB = stA + A_ST;
        const uint32_t kbb = ks * 32;
        #pragma unroll
        for (int mt = 0; mt < 4; mt++)
            LDSM_X4(af[fb][mt][0], af[fb][mt][1], af[fb][mt][2], af[fb][mt][3],
                    stA + aoff + mt * (16 * ROWB) + kbb);
        #pragma unroll
        for (int ntp = 0; ntp < 4; ntp++)
            LDSM_X4(bf[fb][ntp][0], bf[fb][ntp][1], bf[fb][ntp][2], bf[fb][ntp][3],
                    stB + boff + ntp * (16 * ROWB) + kbb);
    };

    auto hmma_all = [&](int fb) {
        #pragma unroll
        for (int mt = 0; mt < 4; mt++)
            #pragma unroll
            for (int ntp = 0; ntp < 4; ntp++) {
                mma_f16(acc[mt][2 * ntp],     af[fb][mt][0], af[fb][mt][1], af[fb][mt][2],
                        af[fb][mt][3], bf[fb][ntp][0], bf[fb][ntp][1]);
                mma_f16(acc[mt][2 * ntp + 1], af[fb][mt][0], af[fb][mt][1], af[fb][mt][2],
                        af[fb][mt][3], bf[fb][ntp][2], bf[fb][ntp][3]);
            }
    };

    CP_WAIT(2);
    __syncthreads();
    ldsm_frags(sbase + 1024, 0, 0);

    #pragma unroll 1
    for (int c = 0; c < KCH; ++c) {
        const uint32_t stA = sbase + 1024 + (c % NST) * STG;

        #pragma unroll
        for (int ks = 0; ks < 3; ks++) {
            ldsm_frags(stA, ks + 1, (ks + 1) & 1);
            hmma_all(ks & 1);
        }

        if (c < KCH - 1) {
            if (c < KCH - 2) { CP_WAIT(1); } else { CP_WAIT(0); }
            __syncthreads();
            if (c + 3 < KCH) load_chunk(c + 3, (c + 3) % NST);
            ldsm_frags(sbase + 1024 + ((c + 1) % NST) * STG, 0, 0);
        }

        hmma_all(1);
    }

    // ---- Epilogue ----
    const size_t matsz = (size_t)BWIN * NH * LW * HD;
    __half* base = g_qkv + (size_t)mat * matsz;

    if (mat < 2) {
        // Q, K: direct half2 stores into [l][d] (contiguous d pairs)
        #pragma unroll
        for (int mt = 0; mt < 4; mt++) {
            const int r0 = m0 + wm * 64 + mt * 16 + (lane >> 2);
            #pragma unroll
            for (int nt = 0; nt < 8; nt++) {
                const int nloc = wn * 64 + nt * 8 + 2 * (lane & 3);
                const int nim = nb + nloc;
                const int h = nim >> 6, d = nim & 63;
                const float bb0 = sBias[nloc], bb1 = sBias[nloc + 1];
                #pragma unroll
                for (int hf = 0; hf < 2; hf++) {
                    const int rr = r0 + hf * 8;
                    const int bw = rr >> 6, l = rr & 63;
                    const size_t o = (((size_t)bw * NH + h) * LW + l) * HD + d;
                    *reinterpret_cast<__half2*>(&base[o]) =
                        __floats2half2_rn(acc[mt][nt][hf * 2 + 0] + bb0,
                                          acc[mt][nt][hf * 2 + 1] + bb1);
                }
            }
        }
    } else {
        // V: stage transposed [n][m] through the free pipeline smem,
        // then write coalesced 128B rows of [d][l].
        __syncthreads();   // all LDSM reads of stage smem done
        __half* sC = reinterpret_cast<__half*>(smem + 1024);   // 128 x 136 halfs
        #pragma unroll
        for (int mt = 0; mt < 4; mt++) {
            #pragma unroll
            for (int nt = 0; nt < 8; nt++) {
                const int nloc = wn * 64 + nt * 8 + 2 * (lane & 3);
                const float bb0 = sBias[nloc], bb1 = sBias[nloc + 1];
                #pragma unroll
                for (int hf = 0; hf < 2; hf++) {
                    const int ml = wm * 64 + mt * 16 + (lane >> 2) + hf * 8;
                    sC[nloc * SCW + ml] =
                        __float2half_rn(acc[mt][nt][hf * 2 + 0] + bb0);
                    sC[(nloc + 1) * SCW + ml] =
                        __float2half_rn(acc[mt][nt][hf * 2 + 1] + bb1);
                }
            }
        }
        __syncthreads();
        // thread t owns n-row t: head = t>>6, d = t&63; 2 windows of 64 l each
        const int h = (nb >> 6) + (tid >> 6), d = tid & 63;
        #pragma unroll
        for (int ww = 0; ww < 2; ww++) {
            const int bw = (m0 >> 6) + ww;
            __half* dst = base + (((size_t)bw * NH + h) * HD + d) * LW;
            const __half* src = &sC[tid * SCW + ww * 64];
            #pragma unroll
            for (int j = 0; j < 8; j++)
                *reinterpret_cast<uint4*>(dst + j * 8) =
                    *reinterpret_cast<const uint4*>(src + j * 8);
        }
    }
}

// ============================================================================
// Kernel 2: windowed attention, fp16 mma, P in registers.
//   cp.async tile loads (L1 bypass, lower reg pressure), 7 CTAs/SM.
// ============================================================================

__global__ __launch_bounds__(128, 7)
void attn_kernel(const float* __restrict__ bias_table, float* __restrict__ out)
{
    __shared__ __half qs [64 * 72];
    __shared__ __half ksm[64 * 72];
    __shared__ __half vts[64 * 72];   // V^T: [d][j]
    __shared__ float sBias[128];

    const int h = blockIdx.x, b = blockIdx.y;
    const int tid = threadIdx.x, lane = tid & 31, warp = tid >> 5;

    const size_t tile = (size_t)(b * NH + h) * (LW * HD);
    const size_t matsz = (size_t)BWIN * NH * LW * HD;
    const __half* gq = g_qkv + tile;
    const __half* gk = g_qkv + matsz + tile;
    const __half* gv = g_qkv + 2 * matsz + tile;

    const uint32_t sq = smem_u32(qs), sk = smem_u32(ksm), sv = smem_u32(vts);

    // cp.async fill: 512 16B chunks per tile, 4 per thread per tile
    #pragma unroll
    for (int i = 0; i < 4; i++) {
        const int f = i * 128 + tid;
        const int row = f >> 3, c16 = f & 7;
        const uint32_t doff = row * 144 + c16 * 16;
        const size_t goff = (size_t)row * 64 + c16 * 8;
        cp16(sq + doff, gq + goff);
        cp16(sk + doff, gk + goff);
        cp16(sv + doff, gv + goff);
    }
    CP_COMMIT();
    if (tid < 127) sBias[tid] = bias_table[tid * NH + h];
    CP_WAIT(0);
    __syncthreads();

    const int i0 = warp * 16 + (lane >> 2);
    const uint32_t* wQ = reinterpret_cast<const uint32_t*>(qs);
    const uint32_t* wK = reinterpret_cast<const uint32_t*>(ksm);
    const uint32_t* wV = reinterpret_cast<const uint32_t*>(vts);

    float s[8][4];
    #pragma unroll
    for (int nt = 0; nt < 8; nt++)
        #pragma unroll
        for (int j = 0; j < 4; j++) s[nt][j] = 0.f;

    #pragma unroll
    for (int ks = 0; ks < 4; ks++) {
        const int kw = ks * 8 + (lane & 3);
        const uint32_t a0 = wQ[i0 * 36 + kw];
        const uint32_t a1 = wQ[(i0 + 8) * 36 + kw];
        const uint32_t a2 = wQ[i0 * 36 + kw + 4];
        const uint32_t a3 = wQ[(i0 + 8) * 36 + kw + 4];
        #pragma unroll
        for (int nt = 0; nt < 8; nt++) {
            const int col = nt * 8 + (lane >> 2);
            mma_f16(s[nt], a0, a1, a2, a3, wK[col * 36 + kw], wK[col * 36 + kw + 4]);
        }
    }

    float mx0 = -1e30f, mx1 = -1e30f;
    #pragma unroll
    for (int nt = 0; nt < 8; nt++) {
        const int j0 = nt * 8 + 2 * (lane & 3);
        float v00 = s[nt][0] * 0.125f + sBias[i0 - j0 + 63];
        float v01 = s[nt][1] * 0.125f + sBias[i0 - j0 + 62];
        float v10 = s[nt][2] * 0.125f + sBias[i0 + 8 - j0 + 63];
        float v11 = s[nt][3] * 0.125f + sBias[i0 + 8 - j0 + 62];
        s[nt][0] = v00; s[nt][1] = v01; s[nt][2] = v10; s[nt][3] = v11;
        mx0 = fmaxf(mx0, fmaxf(v00, v01));
        mx1 = fmaxf(mx1, fmaxf(v10, v11));
    }
    mx0 = fmaxf(mx0, __shfl_xor_sync(0xffffffffu, mx0, 1));
    mx0 = fmaxf(mx0, __shfl_xor_sync(0xffffffffu, mx0, 2));
    mx1 = fmaxf(mx1, __shfl_xor_sync(0xffffffffu, mx1, 1));
    mx1 = fmaxf(mx1, __shfl_xor_sync(0xffffffffu, mx1, 2));

    float sum0 = 0.f, sum1 = 0.f;
    #pragma unroll
    for (int nt = 0; nt < 8; nt++) {
        s[nt][0] = __expf(s[nt][0] - mx0);
        s[nt][1] = __expf(s[nt][1] - mx0);
        s[nt][2] = __expf(s[nt][2] - mx1);
        s[nt][3] = __expf(s[nt][3] - mx1);
        sum0 += s[nt][0] + s[nt][1];
        sum1 += s[nt][2] + s[nt][3];
    }
    sum0 += __shfl_xor_sync(0xffffffffu, sum0, 1);
    sum0 += __shfl_xor_sync(0xffffffffu, sum0, 2);
    sum1 += __shfl_xor_sync(0xffffffffu, sum1, 1);
    sum1 += __shfl_xor_sync(0xffffffffu, sum1, 2);

    float o[8][4];
    #pragma unroll
    for (int nt = 0; nt < 8; nt++)
        #pragma unroll
        for (int j = 0; j < 4; j++) o[nt][j] = 0.f;

    #pragma unroll
    for (int ks = 0; ks < 4; ks++) {
        __half2 ah[4];
        ah[0] = __floats2half2_rn(s[2 * ks][0],     s[2 * ks][1]);
        ah[1] = __floats2half2_rn(s[2 * ks][2],     s[2 * ks][3]);
        ah[2] = __floats2half2_rn(s[2 * ks + 1][0], s[2 * ks + 1][1]);
        ah[3] = __floats2half2_rn(s[2 * ks + 1][2], s[2 * ks + 1][3]);
        const uint32_t a0 = *reinterpret_cast<uint32_t*>(&ah[0]);
        const uint32_t a1 = *reinterpret_cast<uint32_t*>(&ah[1]);
        const uint32_t a2 = *reinterpret_cast<uint32_t*>(&ah[2]);
        const uint32_t a3 = *reinterpret_cast<uint32_t*>(&ah[3]);
        const int kw = ks * 8 + (lane & 3);
        #pragma unroll
        for (int nt = 0; nt < 8; nt++) {
            const int d = nt * 8 + (lane >> 2);
            mma_f16(o[nt], a0, a1, a2, a3, wV[d * 36 + kw], wV[d * 36 + kw + 4]);
        }
    }

    const float inv0 = 1.0f / sum0;
    const float inv1 = 1.0f / sum1;

    #pragma unroll
    for (int nt = 0; nt < 8; nt++) {
        const int d = nt * 8 + 2 * (lane & 3);
        const size_t o0 = ((size_t)(b * LW + i0)) * CH + h * HD + d;
        const size_t o1 = ((size_t)(b * LW + i0 + 8)) * CH + h * HD + d;
        *reinterpret_cast<float2*>(&out[o0]) = make_float2(o[nt][0] * inv0, o[nt][1] * inv0);
        *reinterpret_cast<float2*>(&out[o1]) = make_float2(o[nt][2] * inv1, o[nt][3] * inv1);
    }
}

// ============================================================================

extern "C" void kernel_launch(void* const* d_in, const int* in_sizes, int n_in,
                              void* d_out, int out_size)
{
    const float* X   = (const float*)d_in[0];
    const float* Wq  = (const float*)d_in[1];
    const float* bq  = (const float*)d_in[2];
    const float* Wk  = (const float*)d_in[3];
    const float* bk  = (const float*)d_in[4];
    const float* Wv  = (const float*)d_in[5];
    const float* bv  = (const float*)d_in[6];
    const float* bt  = (const float*)d_in[7];
    float* out = (float*)d_out;

    static cudaStream_t s2 = nullptr;
    static cudaEvent_t e0 = nullptr, e1 = nullptr;
    if (s2 == nullptr) {
        cudaStreamCreateWithFlags(&s2, cudaStreamNonBlocking);
        cudaEventCreateWithFlags(&e0, cudaEventDisableTiming);
        cudaEventCreateWithFlags(&e1, cudaEventDisableTiming);
        cudaFuncSetAttribute(qkv_gemm, cudaFuncAttributeMaxDynamicSharedMemorySize,
                             GEMM_SMEM);
    }

    // prep_w (s2) concurrent with conv_x (stream 0); join before GEMM.
    cudaEventRecord(e0, 0);
    cudaStreamWaitEvent(s2, e0, 0);
    prep_w_kernel<<<dim3(32, 32, 3), 256, 0, s2>>>(Wq, Wk, Wv);
    cudaEventRecord(e1, s2);

    conv_x_kernel<<<(BWIN * LW * CH) / (256 * 8), 256>>>(X);
    cudaStreamWaitEvent(0, e1, 0);

    qkv_gemm<<<dim3(24, 512), 128, GEMM_SMEM>>>(bq, bk, bv);
    attn_kernel<<<dim3(NH, BWIN), 128>>>(bt, out);
}

// round 15
// speedup vs baseline: 1.5786x; 1.0100x over previous
#include <cuda_runtime.h>
#include <cuda_fp16.h>
#include <cstdint>

#define BWIN 1024   // windows (batch)
#define LW   64     // window length
#define CH   1024   // channels
#define NH   16     // heads
#define HD   64     // head dim

// Scratch: Q,K as [(b*16+h)][l][d]; V as [(b*16+h)][d][l] (transposed)
__device__ __half g_qkv[3ULL * BWIN * NH * LW * HD];     // 384 MiB
__device__ __half g_xh [(size_t)BWIN * LW * CH];         // 128 MiB
__device__ __half g_wh [3ULL * CH * CH];                 // 6 MiB: W^T [mat][n][k]

__device__ __forceinline__ void mma_f16(float c[4],
                                        uint32_t a0, uint32_t a1, uint32_t a2, uint32_t a3,
                                        uint32_t b0, uint32_t b1) {
    asm volatile(
        "mma.sync.aligned.m16n8k16.row.col.f32.f16.f16.f32 "
        "{%0,%1,%2,%3}, {%4,%5,%6,%7}, {%8,%9}, {%0,%1,%2,%3};\n"
        : "+f"(c[0]), "+f"(c[1]), "+f"(c[2]), "+f"(c[3])
        : "r"(a0), "r"(a1), "r"(a2), "r"(a3), "r"(b0), "r"(b1));
}

#define LDSM_X4(r0, r1, r2, r3, addr) \
    asm volatile("ldmatrix.sync.aligned.m8n8.x4.shared.b16 {%0,%1,%2,%3}, [%4];" \
                 : "=r"(r0), "=r"(r1), "=r"(r2), "=r"(r3) : "r"(addr))

__device__ __forceinline__ uint32_t smem_u32(const void* p) {
    uint32_t a;
    asm("{ .reg .u64 t; cvta.to.shared.u64 t, %1; cvt.u32.u64 %0, t; }" : "=r"(a) : "l"(p));
    return a;
}

__device__ __forceinline__ void cp16(uint32_t dst, const void* src) {
    asm volatile("cp.async.cg.shared.global [%0], [%1], 16;" :: "r"(dst), "l"(src) : "memory");
}
#define CP_COMMIT() asm volatile("cp.async.commit_group;" ::: "memory")
#define CP_WAIT(n)  asm volatile("cp.async.wait_group %0;" :: "n"(n) : "memory")

// ============================================================================
// Prologue: X -> half; W -> half transposed [mat][n][k]
// ============================================================================
__global__ __launch_bounds__(256)
void conv_x_kernel(const float* __restrict__ X)
{
    const size_t i = ((size_t)blockIdx.x * 256 + threadIdx.x) * 8;
    float4 v0 = *reinterpret_cast<const float4*>(X + i);
    float4 v1 = *reinterpret_cast<const float4*>(X + i + 4);
    __half2 h[4];
    h[0] = __floats2half2_rn(v0.x, v0.y);
    h[1] = __floats2half2_rn(v0.z, v0.w);
    h[2] = __floats2half2_rn(v1.x, v1.y);
    h[3] = __floats2half2_rn(v1.z, v1.w);
    *reinterpret_cast<uint4*>(&g_xh[i]) = *reinterpret_cast<uint4*>(h);
}

__global__ __launch_bounds__(256)
void prep_w_kernel(const float* __restrict__ Wq, const float* __restrict__ Wk,
                   const float* __restrict__ Wv)
{
    __shared__ float t[32][33];
    const int mat = blockIdx.z;
    const float* W = (mat == 0) ? Wq : (mat == 1 ? Wk : Wv);
    const int k0 = blockIdx.x * 32, n0 = blockIdx.y * 32;
    const int tx = threadIdx.x & 31, ty = threadIdx.x >> 5;
    #pragma unroll
    for (int i = 0; i < 4; i++) {
        const int r = ty + i * 8;
        t[r][tx] = W[(size_t)(k0 + r) * CH + n0 + tx];
    }
    __syncthreads();
    __half* dst = g_wh + (size_t)mat * CH * CH;
    #pragma unroll
    for (int i = 0; i < 4; i++) {
        const int r = ty + i * 8;
        dst[(size_t)(n0 + r) * CH + k0 + tx] = __float2half_rn(t[tx][r]);
    }
}

// ============================================================================
// Kernel 1: QKV GEMM (r10 config — best known, direct-scatter epilogue).
//   CTA tile 128x128, 128 thr (4 warps 2x2, warp tile 64x64), k-chunk 64,
//   3-stage cp.async pipeline, frag double-buffer, 2 CTAs/SM, 16 barriers.
//   Grid (24, 512), x = {mat x n-tile} fastest for L2 A-reuse.
// ============================================================================

#define ROWB 144              // bytes per smem row (64 halfs + 8 pad)
#define A_ST (128 * ROWB)     // 18432
#define STG  (2 * A_ST)       // 36864
#define NST  3
#define KCH  16               // chunks of k=64
#define GEMM_SMEM (1024 + NST * STG)   // 111616 B

__global__ __launch_bounds__(128, 2)
void qkv_gemm(const float* __restrict__ bq, const float* __restrict__ bk,
              const float* __restrict__ bv)
{
    extern __shared__ char smem[];
    float* sBias = reinterpret_cast<float*>(smem);
    const uint32_t sbase = smem_u32(smem);

    const int tid = threadIdx.x;
    const int lane = tid & 31;
    const int warp = tid >> 5;
    const int wm = warp & 1, wn = warp >> 1;

    const int mat = blockIdx.x >> 3;
    const int nb  = (blockIdx.x & 7) * 128;
    const int m0  = blockIdx.y * 128;
    const float* bias = (mat == 0) ? bq : (mat == 1 ? bk : bv);
    sBias[tid] = bias[nb + tid];

    const __half* gA = g_xh + (size_t)m0 * CH;
    const __half* gB = g_wh + (size_t)mat * CH * CH + (size_t)nb * CH;

    const int rw = tid >> 3, cw = tid & 7;   // copies: rows rw + i*16, 16B-col cw

    auto load_chunk = [&](int kc, int s) {
        const uint32_t stA = sbase + 1024 + s * STG;
        const uint32_t stB = stA + A_ST;
        #pragma unroll
        for (int i = 0; i < 8; i++) {
            const int row = rw + i * 16;
            cp16(stA + row * ROWB + cw * 16, gA + (size_t)row * CH + kc * 64 + cw * 8);
            cp16(stB + row * ROWB + cw * 16, gB + (size_t)row * CH + kc * 64 + cw * 8);
        }
        CP_COMMIT();
    };

    load_chunk(0, 0);
    load_chunk(1, 1);
    load_chunk(2, 2);

    float acc[4][8][4];
    #pragma unroll
    for (int mt = 0; mt < 4; mt++)
        #pragma unroll
        for (int nt = 0; nt < 8; nt++)
            #pragma unroll
            for (int j = 0; j < 4; j++) acc[mt][nt][j] = 0.f;

    const uint32_t aoff = (wm * 64 + (lane & 15)) * ROWB + ((lane >> 4) << 4);
    const uint32_t boff = (wn * 64 + (lane & 7) + ((lane >> 4) << 3)) * ROWB
                        + (((lane >> 3) & 1) << 4);

    uint32_t af[2][4][4], bf[2][4][4];

    auto ldsm_frags = [&](uint32_t stA, int ks, int fb) {
        const uint32_t stB = stA + A_ST;
        const uint32_t kbb = ks * 32;
        #pragma unroll
        for (int mt = 0; mt < 4; mt++)
            LDSM_X4(af[fb][mt][0], af[fb][mt][1], af[fb][mt][2], af[fb][mt][3],
                    stA + aoff + mt * (16 * ROWB) + kbb);
        #pragma unroll
        for (int ntp = 0; ntp < 4; ntp++)
            LDSM_X4(bf[fb][ntp][0], bf[fb][ntp][1], bf[fb][ntp][2], bf[fb][ntp][3],
                    stB + boff + ntp * (16 * ROWB) + kbb);
    };

    auto hmma_all = [&](int fb) {
        #pragma unroll
        for (int mt = 0; mt < 4; mt++)
            #pragma unroll
            for (int ntp = 0; ntp < 4; ntp++) {
                mma_f16(acc[mt][2 * ntp],     af[fb][mt][0], af[fb][mt][1], af[fb][mt][2],
                        af[fb][mt][3], bf[fb][ntp][0], bf[fb][ntp][1]);
                mma_f16(acc[mt][2 * ntp + 1], af[fb][mt][0], af[fb][mt][1], af[fb][mt][2],
                        af[fb][mt][3], bf[fb][ntp][2], bf[fb][ntp][3]);
            }
    };

    CP_WAIT(2);
    __syncthreads();
    ldsm_frags(sbase + 1024, 0, 0);

    #pragma unroll 1
    for (int c = 0; c < KCH; ++c) {
        const uint32_t stA = sbase + 1024 + (c % NST) * STG;

        #pragma unroll
        for (int ks = 0; ks < 3; ks++) {
            ldsm_frags(stA, ks + 1, (ks + 1) & 1);
            hmma_all(ks & 1);
        }

        if (c < KCH - 1) {
            if (c < KCH - 2) { CP_WAIT(1); } else { CP_WAIT(0); }
            __syncthreads();
            if (c + 3 < KCH) load_chunk(c + 3, (c + 3) % NST);
            ldsm_frags(sbase + 1024 + ((c + 1) % NST) * STG, 0, 0);
        }

        hmma_all(1);
    }

    // Epilogue (r10 direct): +bias, fp16, scatter. Q,K -> [l][d]; V -> [d][l].
    const size_t matsz = (size_t)BWIN * NH * LW * HD;
    __half* base = g_qkv + (size_t)mat * matsz;
    #pragma unroll
    for (int mt = 0; mt < 4; mt++) {
        const int r0 = m0 + wm * 64 + mt * 16 + (lane >> 2);
        #pragma unroll
        for (int nt = 0; nt < 8; nt++) {
            const int nloc = wn * 64 + nt * 8 + 2 * (lane & 3);
            const int nim = nb + nloc;
            const int h = nim >> 6, d = nim & 63;
            const float bb0 = sBias[nloc], bb1 = sBias[nloc + 1];
            #pragma unroll
            for (int hf = 0; hf < 2; hf++) {
                const int rr = r0 + hf * 8;
                const int bw = rr >> 6, l = rr & 63;
                const float v0 = acc[mt][nt][hf * 2 + 0] + bb0;
                const float v1 = acc[mt][nt][hf * 2 + 1] + bb1;
                if (mat < 2) {
                    const size_t o = (((size_t)bw * NH + h) * LW + l) * HD + d;
                    *reinterpret_cast<__half2*>(&base[o]) = __floats2half2_rn(v0, v1);
                } else {
                    const size_t o = (((size_t)bw * NH + h) * HD + d) * LW + l;
                    base[o]      = __float2half_rn(v0);
                    base[o + LW] = __float2half_rn(v1);
                }
            }
        }
    }
}

// ============================================================================
// Kernel 2: windowed attention, fp16 mma, P in registers.
//   cp.async tile loads (L1 bypass, lower reg pressure), 7 CTAs/SM.
// ============================================================================

__global__ __launch_bounds__(128, 7)
void attn_kernel(const float* __restrict__ bias_table, float* __restrict__ out)
{
    __shared__ __half qs [64 * 72];
    __shared__ __half ksm[64 * 72];
    __shared__ __half vts[64 * 72];   // V^T: [d][j]
    __shared__ float sBias[128];

    const int h = blockIdx.x, b = blockIdx.y;
    const int tid = threadIdx.x, lane = tid & 31, warp = tid >> 5;

    const size_t tile = (size_t)(b * NH + h) * (LW * HD);
    const size_t matsz = (size_t)BWIN * NH * LW * HD;
    const __half* gq = g_qkv + tile;
    const __half* gk = g_qkv + matsz + tile;
    const __half* gv = g_qkv + 2 * matsz + tile;

    const uint32_t sq = smem_u32(qs), sk = smem_u32(ksm), sv = smem_u32(vts);

    // cp.async fill: 512 16B chunks per tile, 4 per thread per tile
    #pragma unroll
    for (int i = 0; i < 4; i++) {
        const int f = i * 128 + tid;
        const int row = f >> 3, c16 = f & 7;
        const uint32_t doff = row * 144 + c16 * 16;
        const size_t goff = (size_t)row * 64 + c16 * 8;
        cp16(sq + doff, gq + goff);
        cp16(sk + doff, gk + goff);
        cp16(sv + doff, gv + goff);
    }
    CP_COMMIT();
    if (tid < 127) sBias[tid] = bias_table[tid * NH + h];
    CP_WAIT(0);
    __syncthreads();

    const int i0 = warp * 16 + (lane >> 2);
    const uint32_t* wQ = reinterpret_cast<const uint32_t*>(qs);
    const uint32_t* wK = reinterpret_cast<const uint32_t*>(ksm);
    const uint32_t* wV = reinterpret_cast<const uint32_t*>(vts);

    float s[8][4];
    #pragma unroll
    for (int nt = 0; nt < 8; nt++)
        #pragma unroll
        for (int j = 0; j < 4; j++) s[nt][j] = 0.f;

    #pragma unroll
    for (int ks = 0; ks < 4; ks++) {
        const int kw = ks * 8 + (lane & 3);
        const uint32_t a0 = wQ[i0 * 36 + kw];
        const uint32_t a1 = wQ[(i0 + 8) * 36 + kw];
        const uint32_t a2 = wQ[i0 * 36 + kw + 4];
        const uint32_t a3 = wQ[(i0 + 8) * 36 + kw + 4];
        #pragma unroll
        for (int nt = 0; nt < 8; nt++) {
            const int col = nt * 8 + (lane >> 2);
            mma_f16(s[nt], a0, a1, a2, a3, wK[col * 36 + kw], wK[col * 36 + kw + 4]);
        }
    }

    float mx0 = -1e30f, mx1 = -1e30f;
    #pragma unroll
    for (int nt = 0; nt < 8; nt++) {
        const int j0 = nt * 8 + 2 * (lane & 3);
        float v00 = s[nt][0] * 0.125f + sBias[i0 - j0 + 63];
        float v01 = s[nt][1] * 0.125f + sBias[i0 - j0 + 62];
        float v10 = s[nt][2] * 0.125f + sBias[i0 + 8 - j0 + 63];
        float v11 = s[nt][3] * 0.125f + sBias[i0 + 8 - j0 + 62];
        s[nt][0] = v00; s[nt][1] = v01; s[nt][2] = v10; s[nt][3] = v11;
        mx0 = fmaxf(mx0, fmaxf(v00, v01));
        mx1 = fmaxf(mx1, fmaxf(v10, v11));
    }
    mx0 = fmaxf(mx0, __shfl_xor_sync(0xffffffffu, mx0, 1));
    mx0 = fmaxf(mx0, __shfl_xor_sync(0xffffffffu, mx0, 2));
    mx1 = fmaxf(mx1, __shfl_xor_sync(0xffffffffu, mx1, 1));
    mx1 = fmaxf(mx1, __shfl_xor_sync(0xffffffffu, mx1, 2));

    float sum0 = 0.f, sum1 = 0.f;
    #pragma unroll
    for (int nt = 0; nt < 8; nt++) {
        s[nt][0] = __expf(s[nt][0] - mx0);
        s[nt][1] = __expf(s[nt][1] - mx0);
        s[nt][2] = __expf(s[nt][2] - mx1);
        s[nt][3] = __expf(s[nt][3] - mx1);
        sum0 += s[nt][0] + s[nt][1];
        sum1 += s[nt][2] + s[nt][3];
    }
    sum0 += __shfl_xor_sync(0xffffffffu, sum0, 1);
    sum0 += __shfl_xor_sync(0xffffffffu, sum0, 2);
    sum1 += __shfl_xor_sync(0xffffffffu, sum1, 1);
    sum1 += __shfl_xor_sync(0xffffffffu, sum1, 2);

    float o[8][4];
    #pragma unroll
    for (int nt = 0; nt < 8; nt++)
        #pragma unroll
        for (int j = 0; j < 4; j++) o[nt][j] = 0.f;

    #pragma unroll
    for (int ks = 0; ks < 4; ks++) {
        __half2 ah[4];
        ah[0] = __floats2half2_rn(s[2 * ks][0],     s[2 * ks][1]);
        ah[1] = __floats2half2_rn(s[2 * ks][2],     s[2 * ks][3]);
        ah[2] = __floats2half2_rn(s[2 * ks + 1][0], s[2 * ks + 1][1]);
        ah[3] = __floats2half2_rn(s[2 * ks + 1][2], s[2 * ks + 1][3]);
        const uint32_t a0 = *reinterpret_cast<uint32_t*>(&ah[0]);
        const uint32_t a1 = *reinterpret_cast<uint32_t*>(&ah[1]);
        const uint32_t a2 = *reinterpret_cast<uint32_t*>(&ah[2]);
        const uint32_t a3 = *reinterpret_cast<uint32_t*>(&ah[3]);
        const int kw = ks * 8 + (lane & 3);
        #pragma unroll
        for (int nt = 0; nt < 8; nt++) {
            const int d = nt * 8 + (lane >> 2);
            mma_f16(o[nt], a0, a1, a2, a3, wV[d * 36 + kw], wV[d * 36 + kw + 4]);
        }
    }

    const float inv0 = 1.0f / sum0;
    const float inv1 = 1.0f / sum1;

    #pragma unroll
    for (int nt = 0; nt < 8; nt++) {
        const int d = nt * 8 + 2 * (lane & 3);
        const size_t o0 = ((size_t)(b * LW + i0)) * CH + h * HD + d;
        const size_t o1 = ((size_t)(b * LW + i0 + 8)) * CH + h * HD + d;
        *reinterpret_cast<float2*>(&out[o0]) = make_float2(o[nt][0] * inv0, o[nt][1] * inv0);
        *reinterpret_cast<float2*>(&out[o1]) = make_float2(o[nt][2] * inv1, o[nt][3] * inv1);
    }
}

// ============================================================================

extern "C" void kernel_launch(void* const* d_in, const int* in_sizes, int n_in,
                              void* d_out, int out_size)
{
    const float* X   = (const float*)d_in[0];
    const float* Wq  = (const float*)d_in[1];
    const float* bq  = (const float*)d_in[2];
    const float* Wk  = (const float*)d_in[3];
    const float* bk  = (const float*)d_in[4];
    const float* Wv  = (const float*)d_in[5];
    const float* bv  = (const float*)d_in[6];
    const float* bt  = (const float*)d_in[7];
    float* out = (float*)d_out;

    static cudaStream_t s2 = nullptr;
    static cudaEvent_t e0 = nullptr, e1 = nullptr;
    if (s2 == nullptr) {
        cudaStreamCreateWithFlags(&s2, cudaStreamNonBlocking);
        cudaEventCreateWithFlags(&e0, cudaEventDisableTiming);
        cudaEventCreateWithFlags(&e1, cudaEventDisableTiming);
        cudaFuncSetAttribute(qkv_gemm, cudaFuncAttributeMaxDynamicSharedMemorySize,
                             GEMM_SMEM);
    }

    // prep_w (s2) concurrent with conv_x (stream 0); join before GEMM.
    cudaEventRecord(e0, 0);
    cudaStreamWaitEvent(s2, e0, 0);
    prep_w_kernel<<<dim3(32, 32, 3), 256, 0, s2>>>(Wq, Wk, Wv);
    cudaEventRecord(e1, s2);

    conv_x_kernel<<<(BWIN * LW * CH) / (256 * 8), 256>>>(X);
    cudaStreamWaitEvent(0, e1, 0);

    qkv_gemm<<<dim3(24, 512), 128, GEMM_SMEM>>>(bq, bk, bv);
    attn_kernel<<<dim3(NH, BWIN), 128>>>(bt, out);
}